// round 10
// baseline (speedup 1.0000x reference)
#include <cuda_runtime.h>
#include <cuda_bf16.h>
#include <cstdint>
#include <cstring>
#include <math.h>

#define NN 100000
#define NE 1600000
#define NF 500
#define NH 128
#define NC 40
#define SCAN_B 512
#define NBLK ((NN + SCAN_B - 1) / SCAN_B)   // 196

// ---------------- static device scratch (no allocs allowed) ----------------
__device__ float   g_S[NN * NH];      // support = h @ W (fp32 GEMM output)
__device__ float   g_A4[NN * NC];     // layer-4 aggregate
__device__ float   g_W4p[128 * 128];  // W4 zero-padded to 128 cols
__device__ __align__(16) uint8_t g_Wq1[4][128 * 512];  // weights quantized, [n][k]
__device__ __align__(16) uint8_t g_Wq2[4][128 * 512];
__device__ float   g_sb[4][128];      // weight column scales
__device__ __align__(16) uint8_t g_Hq1a[NN * 128];
__device__ __align__(16) uint8_t g_Hq2a[NN * 128];
__device__ __align__(16) uint8_t g_Hq1b[NN * 128];
__device__ __align__(16) uint8_t g_Hq2b[NN * 128];
__device__ float   g_saX[NN], g_invX[NN];  // x row scales
__device__ float   g_saA[NN], g_saB[NN];   // hidden row scales
__device__ int     g_deg[NN];
__device__ int     g_cur[NN];
__device__ int     g_rp[NN + 1];
__device__ int     g_cs[NE];
__device__ float   g_ws[NE];
__device__ int     g_bsum[NBLK];

// ---------------- helpers ----------------
__device__ __forceinline__ uint32_t smem_u32(const void* p) {
    uint32_t a;
    asm("{ .reg .u64 t; cvta.to.shared.u64 t, %1; cvt.u32.u64 %0, t; }" : "=r"(a) : "l"(p));
    return a;
}
__device__ __forceinline__ uint32_t pack4(int a, int b, int c, int d) {
    return (uint32_t)(a & 0xFF) | ((uint32_t)(b & 0xFF) << 8) |
           ((uint32_t)(c & 0xFF) << 16) | ((uint32_t)(d & 0xFF) << 24);
}
__device__ __forceinline__ void q8pair(float v, float inv, int& q1, int& q2) {
    float t = v * inv;
    int a = __float2int_rn(t);
    a = max(-127, min(127, a));
    int r = __float2int_rn((t - (float)a) * 256.f);
    q1 = a;
    q2 = max(-128, min(127, r));
}
#define LDMX4(r0, r1, r2, r3, a) \
    asm volatile("ldmatrix.sync.aligned.m8n8.x4.shared.b16 {%0,%1,%2,%3}, [%4];" \
                 : "=r"(r0), "=r"(r1), "=r"(r2), "=r"(r3) : "r"(a))
#define MMAS8(d, a0, a1, a2, a3, b0v, b1v) \
    asm volatile("mma.sync.aligned.m16n8k32.row.col.s32.s8.s8.s32 " \
                 "{%0,%1,%2,%3}, {%4,%5,%6,%7}, {%8,%9}, {%0,%1,%2,%3};" \
                 : "+r"((d)[0]), "+r"((d)[1]), "+r"((d)[2]), "+r"((d)[3]) \
                 : "r"(a0), "r"(a1), "r"(a2), "r"(a3), "r"(b0v), "r"(b1v))

// ---------------- CSR construction ----------------
__global__ void k_zero() {
    int i = blockIdx.x * blockDim.x + threadIdx.x;
    if (i < NN) { g_deg[i] = 0; g_cur[i] = 0; }
}
__global__ void k_count(const int* __restrict__ row) {
    int e = blockIdx.x * blockDim.x + threadIdx.x;
    if (e < NE) atomicAdd(&g_deg[row[e]], 1);
}
__global__ void k_scan1() {
    __shared__ int s[SCAN_B];
    int i = blockIdx.x * SCAN_B + threadIdx.x;
    int v = (i < NN) ? g_deg[i] : 0;
    s[threadIdx.x] = v;
    __syncthreads();
    for (int off = 1; off < SCAN_B; off <<= 1) {
        int t = (threadIdx.x >= off) ? s[threadIdx.x - off] : 0;
        __syncthreads();
        s[threadIdx.x] += t;
        __syncthreads();
    }
    if (i < NN) g_rp[i] = s[threadIdx.x];
    if (threadIdx.x == SCAN_B - 1) g_bsum[blockIdx.x] = s[SCAN_B - 1];
}
__global__ void k_scan2() {
    __shared__ int s[256];
    int v = (threadIdx.x < NBLK) ? g_bsum[threadIdx.x] : 0;
    s[threadIdx.x] = v;
    __syncthreads();
    for (int off = 1; off < 256; off <<= 1) {
        int t = (threadIdx.x >= off) ? s[threadIdx.x - off] : 0;
        __syncthreads();
        s[threadIdx.x] += t;
        __syncthreads();
    }
    if (threadIdx.x < NBLK) g_bsum[threadIdx.x] = s[threadIdx.x] - v;
}
__global__ void k_scan3() {
    int i = blockIdx.x * SCAN_B + threadIdx.x;
    if (i < NN) g_rp[i] = g_rp[i] - g_deg[i] + g_bsum[blockIdx.x];
    if (i == 0) g_rp[NN] = NE;
}
__global__ void k_scatter(const int* __restrict__ row, const int* __restrict__ col,
                          const float* __restrict__ w) {
    int e = blockIdx.x * blockDim.x + threadIdx.x;
    if (e < NE) {
        int r = row[e];
        int pos = g_rp[r] + atomicAdd(&g_cur[r], 1);
        g_cs[pos] = col[e];
        g_ws[pos] = w[e];
    }
}
__global__ void k_padw4(const float* __restrict__ W4) {
    int i = blockIdx.x * blockDim.x + threadIdx.x;   // 128*128
    int k = i >> 7, n = i & 127;
    g_W4p[i] = (n < NC) ? W4[k * NC + n] : 0.f;
}

// ---------------- x row scales: warp per row ----------------
__global__ __launch_bounds__(256) void k_rowmax(const float* __restrict__ x) {
    int m = (blockIdx.x * 256 + threadIdx.x) >> 5;
    if (m >= NN) return;
    int lane = threadIdx.x & 31;
    float mx = 0.f;
    for (int k = lane; k < NF; k += 32) mx = fmaxf(mx, fabsf(x[(size_t)m * NF + k]));
#pragma unroll
    for (int o = 16; o; o >>= 1) mx = fmaxf(mx, __shfl_xor_sync(0xffffffffu, mx, o));
    if (lane == 0) {
        g_saX[m]  = mx / 127.f;
        g_invX[m] = (mx > 0.f) ? 127.f / mx : 0.f;
    }
}

// ---------------- weight quantization: warp per output column n ----------------
// W: [K][128] fp32 -> q1/q2 [n][512] int8 (k-major rows), col scale.
__global__ __launch_bounds__(256) void k_quantW(const float* __restrict__ W, int K,
                                                uint8_t* __restrict__ q1o,
                                                uint8_t* __restrict__ q2o,
                                                float* __restrict__ sb) {
    int n = blockIdx.x * 8 + (threadIdx.x >> 5);
    if (n >= 128) return;
    int lane = threadIdx.x & 31;
    float mx = 0.f;
    for (int k = lane; k < K; k += 32) mx = fmaxf(mx, fabsf(W[(size_t)k * 128 + n]));
#pragma unroll
    for (int o = 16; o; o >>= 1) mx = fmaxf(mx, __shfl_xor_sync(0xffffffffu, mx, o));
    float inv = (mx > 0.f) ? 127.f / mx : 0.f;
    if (lane == 0) sb[n] = mx / 127.f;
    int base = lane * 16;
    uint32_t w1[4], w2[4];
#pragma unroll
    for (int j = 0; j < 4; j++) {
        int qa[4], qb[4];
#pragma unroll
        for (int t = 0; t < 4; t++) {
            int k = base + j * 4 + t;
            float v = (k < K) ? W[(size_t)k * 128 + n] : 0.f;
            q8pair(v, inv, qa[t], qb[t]);
        }
        w1[j] = pack4(qa[0], qa[1], qa[2], qa[3]);
        w2[j] = pack4(qb[0], qb[1], qb[2], qb[3]);
    }
    *(uint4*)(q1o + (size_t)n * 512 + base) = make_uint4(w1[0], w1[1], w1[2], w1[3]);
    *(uint4*)(q2o + (size_t)n * 512 + base) = make_uint4(w2[0], w2[1], w2[2], w2[3]);
}

// ---------------- int8 dual-word split tensor GEMM ----------------
// C[M,128] = A[M,K] @ W[K,128].  C = sa[m]*sb[n]*(acc1 + acc2/256).
// MODE 0: A fp32 (quantize in fill, using Ainv row scales).
// MODE 1: A pre-quantized (Aq1/Aq2, row stride 128, K must be 128).
// CTA: 128x128 tile, BK=32 (bytes), 8 warps 4m x 2n, warp tile 32x64.
// LDA=48: multiple of 16 (ldmatrix row alignment) and conflict-free (stride 12 banks).
#define LDA 48
#define Q8_PART  (128 * LDA)
#define Q8_STAGE (4 * Q8_PART)
#define Q8_SMEM  (2 * Q8_STAGE)      // 49152 bytes (dynamic)
template<int MODE>
__global__ __launch_bounds__(256, 1) void k_gemm_q8(
    const float* __restrict__ Afp, const float* __restrict__ Ainv,
    const uint8_t* __restrict__ Aq1, const uint8_t* __restrict__ Aq2,
    const float* __restrict__ Asc,
    const uint8_t* __restrict__ Bq1, const uint8_t* __restrict__ Bq2,
    const float* __restrict__ Bsc,
    float* __restrict__ C, int M, int K) {
    extern __shared__ __align__(16) uint8_t smq[];   // [stage][part][128*LDA]
    __shared__ float ssb[128];

    const int tid  = threadIdx.x;
    const int wid  = tid >> 5, lane = tid & 31;
    const int m0   = blockIdx.x * 128;
    const int wm   = (wid & 3) * 32;
    const int wn   = (wid >> 2) * 64;

    const int lr  = lane & 7;
    const int grp = lane >> 3;
    const int aRow  = (grp & 1) * 8 + lr;   // A: m offset
    const int aColB = (grp >> 1) * 16;      // A: k byte offset
    const int bRow  = (grp >> 1) * 8 + lr;  // B: n offset
    const int bColB = (grp & 1) * 16;       // B: k byte offset

    // fill indexing
    const int fqA = (tid & 7) * 4;          // A: 4 k-elements/bytes
    const int frA = tid >> 3;               // A row 0..31 (x4 stride 32)
    const int nB  = tid >> 1;               // B n-row 0..127
    const int kbB = (tid & 1) * 16;         // B k-byte half

    const uint32_t uS = smem_u32(smq);

    int acc1[2][8][4], acc2[2][8][4];
#pragma unroll
    for (int i = 0; i < 2; i++)
#pragma unroll
        for (int j = 0; j < 8; j++)
#pragma unroll
            for (int q = 0; q < 4; q++) { acc1[i][j][q] = 0; acc2[i][j][q] = 0; }

    float invA[4];
#pragma unroll
    for (int i = 0; i < 4; i++) {
        int m = m0 + i * 32 + frA;
        invA[i] = (MODE == 0 && m < M) ? Ainv[m] : 0.f;
    }
    if (tid < 128) ssb[tid] = Bsc[tid];

    const int nchunk = (K + 31) / 32;
    float4   pa[4];                 // MODE 0
    uint32_t pa1[4], pa2[4];        // MODE 1
    uint4    pb1, pb2;

    auto ldg_chunk = [&](int c) {
        const int k0 = c * 32;
        if (MODE == 0) {
            const int k = k0 + fqA;
#pragma unroll
            for (int i = 0; i < 4; i++) {
                int m = m0 + i * 32 + frA;
                float4 v = make_float4(0.f, 0.f, 0.f, 0.f);
                if (m < M) {
                    if (k + 3 < K) v = *(const float4*)(Afp + (size_t)m * K + k);
                    else {
                        const float* ap = Afp + (size_t)m * K;
                        if (k     < K) v.x = ap[k];
                        if (k + 1 < K) v.y = ap[k + 1];
                        if (k + 2 < K) v.z = ap[k + 2];
                        if (k + 3 < K) v.w = ap[k + 3];
                    }
                }
                pa[i] = v;
            }
        } else {
#pragma unroll
            for (int i = 0; i < 4; i++) {
                int m = m0 + i * 32 + frA;
                if (m < M) {
                    pa1[i] = *(const uint32_t*)(Aq1 + (size_t)m * 128 + k0 + fqA);
                    pa2[i] = *(const uint32_t*)(Aq2 + (size_t)m * 128 + k0 + fqA);
                } else { pa1[i] = 0; pa2[i] = 0; }
            }
        }
        pb1 = *(const uint4*)(Bq1 + (size_t)nB * 512 + k0 + kbB);
        pb2 = *(const uint4*)(Bq2 + (size_t)nB * 512 + k0 + kbB);
    };
    auto store_chunk = [&](int stage) {
        uint8_t* dA1 = smq + stage * Q8_STAGE;
        uint8_t* dA2 = dA1 + Q8_PART;
        uint8_t* dB1 = dA1 + 2 * Q8_PART;
        uint8_t* dB2 = dA1 + 3 * Q8_PART;
        if (MODE == 0) {
#pragma unroll
            for (int i = 0; i < 4; i++) {
                int r = i * 32 + frA;
                int q1x, q2x, q1y, q2y, q1z, q2z, q1w, q2w;
                q8pair(pa[i].x, invA[i], q1x, q2x);
                q8pair(pa[i].y, invA[i], q1y, q2y);
                q8pair(pa[i].z, invA[i], q1z, q2z);
                q8pair(pa[i].w, invA[i], q1w, q2w);
                *(uint32_t*)&dA1[r * LDA + fqA] = pack4(q1x, q1y, q1z, q1w);
                *(uint32_t*)&dA2[r * LDA + fqA] = pack4(q2x, q2y, q2z, q2w);
            }
        } else {
#pragma unroll
            for (int i = 0; i < 4; i++) {
                int r = i * 32 + frA;
                *(uint32_t*)&dA1[r * LDA + fqA] = pa1[i];
                *(uint32_t*)&dA2[r * LDA + fqA] = pa2[i];
            }
        }
        *(uint2*)&dB1[nB * LDA + kbB]     = make_uint2(pb1.x, pb1.y);
        *(uint2*)&dB1[nB * LDA + kbB + 8] = make_uint2(pb1.z, pb1.w);
        *(uint2*)&dB2[nB * LDA + kbB]     = make_uint2(pb2.x, pb2.y);
        *(uint2*)&dB2[nB * LDA + kbB + 8] = make_uint2(pb2.z, pb2.w);
    };

    ldg_chunk(0);
    store_chunk(0);
    __syncthreads();

    for (int c = 0; c < nchunk; c++) {
        const bool hasNext = (c + 1 < nchunk);
        if (hasNext) ldg_chunk(c + 1);

        const uint32_t uStage = uS + (uint32_t)(c & 1) * Q8_STAGE;
        const uint32_t uA1 = uStage;
        const uint32_t uA2 = uStage + Q8_PART;
        const uint32_t uB1 = uStage + 2 * Q8_PART;
        const uint32_t uB2 = uStage + 3 * Q8_PART;

        uint32_t a1[2][4], a2[2][4];
#pragma unroll
        for (int mt = 0; mt < 2; mt++) {
            uint32_t off = (uint32_t)((wm + mt * 16 + aRow) * LDA + aColB);
            LDMX4(a1[mt][0], a1[mt][1], a1[mt][2], a1[mt][3], uA1 + off);
            LDMX4(a2[mt][0], a2[mt][1], a2[mt][2], a2[mt][3], uA2 + off);
        }
#pragma unroll
        for (int p = 0; p < 4; p++) {
            uint32_t off = (uint32_t)((wn + p * 16 + bRow) * LDA + bColB);
            uint32_t b1r0, b1r1, b1r2, b1r3, b2r0, b2r1, b2r2, b2r3;
            LDMX4(b1r0, b1r1, b1r2, b1r3, uB1 + off);
            LDMX4(b2r0, b2r1, b2r2, b2r3, uB2 + off);
#pragma unroll
            for (int mt = 0; mt < 2; mt++) {
                MMAS8(acc1[mt][2 * p],     a1[mt][0], a1[mt][1], a1[mt][2], a1[mt][3], b1r0, b1r1);
                MMAS8(acc2[mt][2 * p],     a1[mt][0], a1[mt][1], a1[mt][2], a1[mt][3], b2r0, b2r1);
                MMAS8(acc2[mt][2 * p],     a2[mt][0], a2[mt][1], a2[mt][2], a2[mt][3], b1r0, b1r1);
                MMAS8(acc1[mt][2 * p + 1], a1[mt][0], a1[mt][1], a1[mt][2], a1[mt][3], b1r2, b1r3);
                MMAS8(acc2[mt][2 * p + 1], a1[mt][0], a1[mt][1], a1[mt][2], a1[mt][3], b2r2, b2r3);
                MMAS8(acc2[mt][2 * p + 1], a2[mt][0], a2[mt][1], a2[mt][2], a2[mt][3], b1r2, b1r3);
            }
        }

        if (hasNext) store_chunk((c + 1) & 1);
        __syncthreads();
    }

    // ---- epilogue: dequantize
    const int fr = lane >> 2, fc = (lane & 3) * 2;
    float sa0[2], sa1[2];
#pragma unroll
    for (int mt = 0; mt < 2; mt++) {
        int mA = m0 + wm + mt * 16 + fr;
        sa0[mt] = (mA < M)     ? Asc[mA]     : 0.f;
        sa1[mt] = (mA + 8 < M) ? Asc[mA + 8] : 0.f;
    }
#pragma unroll
    for (int mt = 0; mt < 2; mt++) {
        int r0 = m0 + wm + mt * 16 + fr;
#pragma unroll
        for (int nt = 0; nt < 8; nt++) {
            int c0 = wn + nt * 8 + fc;
            float sb0 = ssb[c0], sb1 = ssb[c0 + 1];
            if (r0 < M) {
                float v0 = sa0[mt] * sb0 * ((float)acc1[mt][nt][0] + (float)acc2[mt][nt][0] * (1.f / 256.f));
                float v1 = sa0[mt] * sb1 * ((float)acc1[mt][nt][1] + (float)acc2[mt][nt][1] * (1.f / 256.f));
                *(float2*)(C + (size_t)r0 * 128 + c0) = make_float2(v0, v1);
            }
            if (r0 + 8 < M) {
                float v2 = sa1[mt] * sb0 * ((float)acc1[mt][nt][2] + (float)acc2[mt][nt][2] * (1.f / 256.f));
                float v3 = sa1[mt] * sb1 * ((float)acc1[mt][nt][3] + (float)acc2[mt][nt][3] * (1.f / 256.f));
                *(float2*)(C + (size_t)(r0 + 8) * 128 + c0) = make_float2(v2, v3);
            }
        }
    }
}

// ---------------- CSR SpMM + bias + relu + QUANTIZE (layers 1-3, F=128) ----------------
__global__ __launch_bounds__(256) void k_spmm_q(const float* __restrict__ S,
                                                uint8_t* __restrict__ Hq1,
                                                uint8_t* __restrict__ Hq2,
                                                float* __restrict__ sa,
                                                const float* __restrict__ bias) {
    int wid  = (blockIdx.x * 256 + threadIdx.x) >> 5;
    if (wid >= NN) return;
    int lane = threadIdx.x & 31;

    int beg = g_rp[wid], end = g_rp[wid + 1];
    const float4* Sv = (const float4*)S;
    float4 acc = make_float4(0.f, 0.f, 0.f, 0.f);
#pragma unroll 4
    for (int e = beg; e < end; e++) {
        int   c = g_cs[e];
        float w = g_ws[e];
        float4 v = Sv[(size_t)c * 32 + lane];
        acc.x += w * v.x; acc.y += w * v.y; acc.z += w * v.z; acc.w += w * v.w;
    }
    float4 b = ((const float4*)bias)[lane];
    acc.x = fmaxf(acc.x + b.x, 0.f); acc.y = fmaxf(acc.y + b.y, 0.f);
    acc.z = fmaxf(acc.z + b.z, 0.f); acc.w = fmaxf(acc.w + b.w, 0.f);

    float mx = fmaxf(fmaxf(acc.x, acc.y), fmaxf(acc.z, acc.w));
#pragma unroll
    for (int o = 16; o; o >>= 1) mx = fmaxf(mx, __shfl_xor_sync(0xffffffffu, mx, o));
    float inv = (mx > 0.f) ? 127.f / mx : 0.f;
    if (lane == 0) sa[wid] = mx / 127.f;

    int q1x, q2x, q1y, q2y, q1z, q2z, q1w, q2w;
    q8pair(acc.x, inv, q1x, q2x);
    q8pair(acc.y, inv, q1y, q2y);
    q8pair(acc.z, inv, q1z, q2z);
    q8pair(acc.w, inv, q1w, q2w);
    ((uint32_t*)Hq1)[(size_t)wid * 32 + lane] = pack4(q1x, q1y, q1z, q1w);
    ((uint32_t*)Hq2)[(size_t)wid * 32 + lane] = pack4(q2x, q2y, q2z, q2w);
}

// ---------------- final SpMM (layer 4, F=40, no quant) ----------------
__global__ __launch_bounds__(256) void k_spmm_f(const float* __restrict__ S,
                                                float* __restrict__ H,
                                                const float* __restrict__ bias) {
    int wid  = (blockIdx.x * 256 + threadIdx.x) >> 5;
    if (wid >= NN) return;
    int lane = threadIdx.x & 31;
    int f    = lane * 4;
    if (f >= NC) return;

    int beg = g_rp[wid], end = g_rp[wid + 1];
    const float4* Sv = (const float4*)S;
    float4 acc = make_float4(0.f, 0.f, 0.f, 0.f);
#pragma unroll 4
    for (int e = beg; e < end; e++) {
        int   c = g_cs[e];
        float w = g_ws[e];
        float4 v = Sv[(size_t)c * 32 + lane];   // S rows 128-wide
        acc.x += w * v.x; acc.y += w * v.y; acc.z += w * v.z; acc.w += w * v.w;
    }
    float4 b = ((const float4*)bias)[lane];
    acc.x += b.x; acc.y += b.y; acc.z += b.z; acc.w += b.w;
    ((float4*)H)[(size_t)wid * (NC / 4) + lane] = acc;
}

// ---------------- log_softmax over 40 classes ----------------
__global__ __launch_bounds__(256) void k_lsm(float* __restrict__ out) {
    int wid = (blockIdx.x * 256 + threadIdx.x) >> 5;
    if (wid >= NN) return;
    int lane = threadIdx.x & 31;
    const float* a = g_A4 + (size_t)wid * NC;
    float v0 = a[lane];
    float v1 = (lane + 32 < NC) ? a[lane + 32] : -1e30f;
    float m = fmaxf(v0, v1);
#pragma unroll
    for (int o = 16; o; o >>= 1) m = fmaxf(m, __shfl_xor_sync(0xffffffffu, m, o));
    float s = expf(v0 - m) + ((lane + 32 < NC) ? expf(v1 - m) : 0.f);
#pragma unroll
    for (int o = 16; o; o >>= 1) s += __shfl_xor_sync(0xffffffffu, s, o);
    float l = m + logf(s);
    out[(size_t)wid * NC + lane] = v0 - l;
    if (lane + 32 < NC) out[(size_t)wid * NC + lane + 32] = v1 - l;
}

// ---------------- launch ----------------
extern "C" void kernel_launch(void* const* d_in, const int* in_sizes, int n_in,
                              void* d_out, int out_size) {
    const float* x  = (const float*)d_in[0];
    const int*   row = (const int*)d_in[1];
    const int*   col = (const int*)d_in[2];
    const float* ew  = (const float*)d_in[3];
    const float* W1 = (const float*)d_in[4];  const float* b1 = (const float*)d_in[5];
    const float* W2 = (const float*)d_in[6];  const float* b2 = (const float*)d_in[7];
    const float* W3 = (const float*)d_in[8];  const float* b3 = (const float*)d_in[9];
    const float* W4 = (const float*)d_in[10]; const float* b4 = (const float*)d_in[11];
    float* out = (float*)d_out;

    void *pS, *pA4, *pW4p, *pWq1, *pWq2, *pSb;
    void *pH1a, *pH2a, *pH1b, *pH2b, *pSaX, *pInvX, *pSaA, *pSaB;
    cudaGetSymbolAddress(&pS, g_S);       cudaGetSymbolAddress(&pA4, g_A4);
    cudaGetSymbolAddress(&pW4p, g_W4p);
    cudaGetSymbolAddress(&pWq1, g_Wq1);   cudaGetSymbolAddress(&pWq2, g_Wq2);
    cudaGetSymbolAddress(&pSb, g_sb);
    cudaGetSymbolAddress(&pH1a, g_Hq1a);  cudaGetSymbolAddress(&pH2a, g_Hq2a);
    cudaGetSymbolAddress(&pH1b, g_Hq1b);  cudaGetSymbolAddress(&pH2b, g_Hq2b);
    cudaGetSymbolAddress(&pSaX, g_saX);   cudaGetSymbolAddress(&pInvX, g_invX);
    cudaGetSymbolAddress(&pSaA, g_saA);   cudaGetSymbolAddress(&pSaB, g_saB);
    float*   S    = (float*)pS;
    float*   A4   = (float*)pA4;
    float*   W4p  = (float*)pW4p;
    uint8_t* Wq1  = (uint8_t*)pWq1;   // [4][128*512]
    uint8_t* Wq2  = (uint8_t*)pWq2;
    float*   sb   = (float*)pSb;      // [4][128]
    uint8_t* H1a  = (uint8_t*)pH1a, *H2a = (uint8_t*)pH2a;
    uint8_t* H1b  = (uint8_t*)pH1b, *H2b = (uint8_t*)pH2b;
    float*   saX  = (float*)pSaX, *invX = (float*)pInvX;
    float*   saA  = (float*)pSaA, *saB  = (float*)pSaB;

    cudaFuncSetAttribute(k_gemm_q8<0>, cudaFuncAttributeMaxDynamicSharedMemorySize, Q8_SMEM);
    cudaFuncSetAttribute(k_gemm_q8<1>, cudaFuncAttributeMaxDynamicSharedMemorySize, Q8_SMEM);

    const int EB = (NE + 255) / 256;
    const int GM = (NN + 127) / 128;
    const int SB = (NN + 7) / 8;

    // CSR build + scale/quant prep
    k_zero<<<(NN + 255) / 256, 256>>>();
    k_count<<<EB, 256>>>(row);
    k_rowmax<<<SB, 256>>>(x);
    k_padw4<<<64, 256>>>(W4);
    k_quantW<<<16, 256>>>(W1, NF, Wq1 + 0 * 65536, Wq2 + 0 * 65536, sb + 0 * 128);
    k_quantW<<<16, 256>>>(W2, NH, Wq1 + 1 * 65536, Wq2 + 1 * 65536, sb + 1 * 128);
    k_quantW<<<16, 256>>>(W3, NH, Wq1 + 2 * 65536, Wq2 + 2 * 65536, sb + 2 * 128);
    k_quantW<<<16, 256>>>(W4p, NH, Wq1 + 3 * 65536, Wq2 + 3 * 65536, sb + 3 * 128);
    // layer-1 GEMM (fp32 A, quantize in fill)
    k_gemm_q8<0><<<GM, 256, Q8_SMEM>>>(x, invX, nullptr, nullptr, saX,
                              Wq1 + 0 * 65536, Wq2 + 0 * 65536, sb + 0 * 128, S, NN, NF);
    k_scan1<<<NBLK, SCAN_B>>>();
    k_scan2<<<1, 256>>>();
    k_scan3<<<NBLK, SCAN_B>>>();
    k_scatter<<<EB, 256>>>(row, col, ew);

    // layer 1 aggregate -> quantized hidden (ping)
    k_spmm_q<<<SB, 256>>>(S, H1a, H2a, saA, b1);
    // layer 2
    k_gemm_q8<1><<<GM, 256, Q8_SMEM>>>(nullptr, nullptr, H1a, H2a, saA,
                              Wq1 + 1 * 65536, Wq2 + 1 * 65536, sb + 1 * 128, S, NN, NH);
    k_spmm_q<<<SB, 256>>>(S, H1b, H2b, saB, b2);
    // layer 3
    k_gemm_q8<1><<<GM, 256, Q8_SMEM>>>(nullptr, nullptr, H1b, H2b, saB,
                              Wq1 + 2 * 65536, Wq2 + 2 * 65536, sb + 2 * 128, S, NN, NH);
    k_spmm_q<<<SB, 256>>>(S, H1a, H2a, saA, b3);
    // layer 4 (padded) + final aggregate + log_softmax
    k_gemm_q8<1><<<GM, 256, Q8_SMEM>>>(nullptr, nullptr, H1a, H2a, saA,
                              Wq1 + 3 * 65536, Wq2 + 3 * 65536, sb + 3 * 128, S, NN, NH);
    k_spmm_f<<<SB, 256>>>(S, A4, b4);
    k_lsm<<<SB, 256>>>(out);
}

// round 11
// speedup vs baseline: 1.9214x; 1.9214x over previous
#include <cuda_runtime.h>
#include <cuda_bf16.h>
#include <cstdint>
#include <cstring>
#include <math.h>

#define NN 100000
#define NE 1600000
#define NF 500
#define NH 128
#define NC 40
#define SCAN_B 512
#define NBLK ((NN + SCAN_B - 1) / SCAN_B)   // 196

// ---------------- static device scratch (no allocs allowed) ----------------
__device__ float g_S[NN * NH];     // support = h @ W
__device__ float g_H[NN * NH];     // hidden ping
__device__ float g_H2[NN * NH];    // hidden pong
__device__ float g_A4[NN * NC];    // layer-4 aggregate (pre log_softmax)
__device__ float g_W4p[128 * 128]; // W4 zero-padded to 128 cols
__device__ int   g_deg[NN];
__device__ int   g_cur[NN];
__device__ int   g_rp[NN + 1];     // CSR row pointers
__device__ int   g_cs[NE];         // CSR col (source node) per edge
__device__ float g_ws[NE];         // CSR edge weight
__device__ int   g_bsum[NBLK];

// ---------------- CSR construction ----------------
__global__ void k_zero() {
    int i = blockIdx.x * blockDim.x + threadIdx.x;
    if (i < NN) { g_deg[i] = 0; g_cur[i] = 0; }
}
__global__ void k_count(const int* __restrict__ row) {
    int e = blockIdx.x * blockDim.x + threadIdx.x;
    if (e < NE) atomicAdd(&g_deg[row[e]], 1);
}
__global__ void k_scan1() {
    __shared__ int s[SCAN_B];
    int i = blockIdx.x * SCAN_B + threadIdx.x;
    int v = (i < NN) ? g_deg[i] : 0;
    s[threadIdx.x] = v;
    __syncthreads();
    for (int off = 1; off < SCAN_B; off <<= 1) {
        int t = (threadIdx.x >= off) ? s[threadIdx.x - off] : 0;
        __syncthreads();
        s[threadIdx.x] += t;
        __syncthreads();
    }
    if (i < NN) g_rp[i] = s[threadIdx.x];
    if (threadIdx.x == SCAN_B - 1) g_bsum[blockIdx.x] = s[SCAN_B - 1];
}
__global__ void k_scan2() {
    __shared__ int s[256];
    int v = (threadIdx.x < NBLK) ? g_bsum[threadIdx.x] : 0;
    s[threadIdx.x] = v;
    __syncthreads();
    for (int off = 1; off < 256; off <<= 1) {
        int t = (threadIdx.x >= off) ? s[threadIdx.x - off] : 0;
        __syncthreads();
        s[threadIdx.x] += t;
        __syncthreads();
    }
    if (threadIdx.x < NBLK) g_bsum[threadIdx.x] = s[threadIdx.x] - v;
}
__global__ void k_scan3() {
    int i = blockIdx.x * SCAN_B + threadIdx.x;
    if (i < NN) g_rp[i] = g_rp[i] - g_deg[i] + g_bsum[blockIdx.x];
    if (i == 0) g_rp[NN] = NE;
}
__global__ void k_scatter(const int* __restrict__ row, const int* __restrict__ col,
                          const float* __restrict__ w) {
    int e = blockIdx.x * blockDim.x + threadIdx.x;
    if (e < NE) {
        int r = row[e];
        int pos = g_rp[r] + atomicAdd(&g_cur[r], 1);
        g_cs[pos] = col[e];
        g_ws[pos] = w[e];
    }
}
__global__ void k_padw4(const float* __restrict__ W4) {
    int i = blockIdx.x * blockDim.x + threadIdx.x;   // 128*128
    int k = i >> 7, n = i & 127;
    g_W4p[i] = (n < NC) ? W4[k * NC + n] : 0.f;
}

// ---------------- bf16-split tensor-core GEMM (mma.sync) ----------------
// C[M,128] = A[M,K] @ W[K,128], fp32 in/out.
// acc += Ah*Bh + Ah*Bl + Al*Bh  (~2^-17 effective precision).
// CTA: 128x128 tile, BK=32, 256 threads = 8 warps (4m x 2n), warp tile 32x64.
// 2-stage double-buffered smem, one sync per chunk; register prefetch.
// MMA issue is TERM-MAJOR: consecutive MMAs always hit distinct accumulators,
// so HMMA latency is pipelined instead of serialized on RAW chains.
#define LDT 40
#define LDB 136
#define OFF_AH 0
#define OFF_AL (128 * LDT)
#define OFF_BH (2 * 128 * LDT)
#define OFF_BL (2 * 128 * LDT + 32 * LDB)
#define STAGE_ELTS (2 * 128 * LDT + 2 * 32 * LDB)     // 18944
#define STAGE_BYTES (STAGE_ELTS * 2)                  // 37888
#define GEMM_SMEM (2 * STAGE_BYTES)                   // 75776

__device__ __forceinline__ uint32_t smem_u32(const void* p) {
    uint32_t a;
    asm("{ .reg .u64 t; cvta.to.shared.u64 t, %1; cvt.u32.u64 %0, t; }" : "=r"(a) : "l"(p));
    return a;
}
__device__ __forceinline__ uint32_t pack2bf(float x, float y) {
    __nv_bfloat162 t = __floats2bfloat162_rn(x, y);
    uint32_t u; memcpy(&u, &t, 4); return u;
}
#define LDMX4(r0, r1, r2, r3, a) \
    asm volatile("ldmatrix.sync.aligned.m8n8.x4.shared.b16 {%0,%1,%2,%3}, [%4];" \
                 : "=r"(r0), "=r"(r1), "=r"(r2), "=r"(r3) : "r"(a))
#define LDMX4T(r0, r1, r2, r3, a) \
    asm volatile("ldmatrix.sync.aligned.m8n8.x4.trans.shared.b16 {%0,%1,%2,%3}, [%4];" \
                 : "=r"(r0), "=r"(r1), "=r"(r2), "=r"(r3) : "r"(a))
#define MMA16816(d, a, b0v, b1v) \
    asm volatile("mma.sync.aligned.m16n8k16.row.col.f32.bf16.bf16.f32 " \
                 "{%0,%1,%2,%3}, {%4,%5,%6,%7}, {%8,%9}, {%0,%1,%2,%3};" \
                 : "+f"((d)[0]), "+f"((d)[1]), "+f"((d)[2]), "+f"((d)[3]) \
                 : "r"((a)[0]), "r"((a)[1]), "r"((a)[2]), "r"((a)[3]), \
                   "r"(b0v), "r"(b1v))

__global__ __launch_bounds__(256, 1) void k_gemm_mma(const float* __restrict__ A,
                                                     const float* __restrict__ W,
                                                     float* __restrict__ C,
                                                     int M, int K) {
    extern __shared__ __align__(16) __nv_bfloat16 smem[];

    const int tid  = threadIdx.x;
    const int wid  = tid >> 5, lane = tid & 31;
    const int m0   = blockIdx.x * 128;
    const int wm   = (wid & 3) * 32;    // warp row base
    const int wn   = (wid >> 2) * 64;   // warp col base

    const int lr  = lane & 7;
    const int grp = lane >> 3;
    const int aRow = (grp & 1) * 8 + lr;   // A: m offset
    const int aCol = (grp >> 1) * 8;       // A: k offset
    const int bK   = (grp & 1) * 8 + lr;   // B: k row (trans)
    const int bN   = (grp >> 1) * 8;       // B: n offset

    const int fqA = (tid & 7) * 4;         // A k within chunk
    const int frA = tid >> 3;              // A row 0..31 (stride 32)
    const int fkB = tid >> 5;              // B k 0..7 (stride 8)
    const int fnB = (tid & 31) * 4;        // B n

    const uint32_t uS0 = smem_u32(smem);

    float acc[2][8][4];
#pragma unroll
    for (int i = 0; i < 2; i++)
#pragma unroll
        for (int j = 0; j < 8; j++)
#pragma unroll
            for (int q = 0; q < 4; q++) acc[i][j][q] = 0.f;

    const int nchunk = (K + 31) / 32;
    float4 pa[4], pb[4];

    auto ldg_chunk = [&](int c) {
        const int k0 = c * 32;
        const int k = k0 + fqA;
#pragma unroll
        for (int i = 0; i < 4; i++) {
            int m = m0 + i * 32 + frA;
            pa[i] = (m < M && k < K) ? *(const float4*)(A + (size_t)m * K + k)
                                     : make_float4(0.f, 0.f, 0.f, 0.f);
        }
#pragma unroll
        for (int i = 0; i < 4; i++) {
            int kk = k0 + fkB + 8 * i;
            pb[i] = (kk < K) ? *(const float4*)(W + (size_t)kk * 128 + fnB)
                             : make_float4(0.f, 0.f, 0.f, 0.f);
        }
    };
    auto store_chunk = [&](int stage) {
        __nv_bfloat16* base = smem + stage * STAGE_ELTS;
        __nv_bfloat16* dAh = base + OFF_AH;
        __nv_bfloat16* dAl = base + OFF_AL;
        __nv_bfloat16* dBh = base + OFF_BH;
        __nv_bfloat16* dBl = base + OFF_BL;
#pragma unroll
        for (int i = 0; i < 4; i++) {
            int r = i * 32 + frA;
            float4 v = pa[i];
            __nv_bfloat162 h01 = __floats2bfloat162_rn(v.x, v.y);
            __nv_bfloat162 h23 = __floats2bfloat162_rn(v.z, v.w);
            float lx = v.x - __bfloat162float(h01.x);
            float ly = v.y - __bfloat162float(h01.y);
            float lz = v.z - __bfloat162float(h23.x);
            float lw = v.w - __bfloat162float(h23.y);
            uint32_t uh01, uh23;
            memcpy(&uh01, &h01, 4); memcpy(&uh23, &h23, 4);
            *(uint2*)&dAh[r * LDT + fqA] = make_uint2(uh01, uh23);
            *(uint2*)&dAl[r * LDT + fqA] = make_uint2(pack2bf(lx, ly), pack2bf(lz, lw));
        }
#pragma unroll
        for (int i = 0; i < 4; i++) {
            int kk = fkB + 8 * i;
            float4 v = pb[i];
            __nv_bfloat162 h01 = __floats2bfloat162_rn(v.x, v.y);
            __nv_bfloat162 h23 = __floats2bfloat162_rn(v.z, v.w);
            float lx = v.x - __bfloat162float(h01.x);
            float ly = v.y - __bfloat162float(h01.y);
            float lz = v.z - __bfloat162float(h23.x);
            float lw = v.w - __bfloat162float(h23.y);
            uint32_t uh01, uh23;
            memcpy(&uh01, &h01, 4); memcpy(&uh23, &h23, 4);
            *(uint2*)&dBh[kk * LDB + fnB] = make_uint2(uh01, uh23);
            *(uint2*)&dBl[kk * LDB + fnB] = make_uint2(pack2bf(lx, ly), pack2bf(lz, lw));
        }
    };

    // -------- prologue: chunk 0 into stage 0 --------
    ldg_chunk(0);
    store_chunk(0);
    __syncthreads();

    for (int c = 0; c < nchunk; c++) {
        const bool hasNext = (c + 1 < nchunk);
        if (hasNext) ldg_chunk(c + 1);          // LDGs fly during MMAs below

        const uint32_t uBase = uS0 + (uint32_t)(c & 1) * STAGE_BYTES;
        const uint32_t uAh = uBase + OFF_AH * 2;
        const uint32_t uAl = uBase + OFF_AL * 2;
        const uint32_t uBh = uBase + OFF_BH * 2;
        const uint32_t uBl = uBase + OFF_BL * 2;

#pragma unroll
        for (int ks = 0; ks < 2; ks++) {
            const int kb = ks * 16;
            uint32_t ah[2][4], al[2][4];
#pragma unroll
            for (int mt = 0; mt < 2; mt++) {
                uint32_t off = (uint32_t)((wm + mt * 16 + aRow) * LDT + kb + aCol) * 2;
                LDMX4(ah[mt][0], ah[mt][1], ah[mt][2], ah[mt][3], uAh + off);
                LDMX4(al[mt][0], al[mt][1], al[mt][2], al[mt][3], uAl + off);
            }
            uint32_t bh[4][4], bl[4][4];
#pragma unroll
            for (int p = 0; p < 4; p++) {
                uint32_t off = (uint32_t)((kb + bK) * LDB + wn + p * 16 + bN) * 2;
                LDMX4T(bh[p][0], bh[p][1], bh[p][2], bh[p][3], uBh + off);
                LDMX4T(bl[p][0], bl[p][1], bl[p][2], bl[p][3], uBl + off);
            }
            // term-major: every consecutive MMA targets a different accumulator;
            // each acc quad revisited only after 15 intervening MMAs.
#pragma unroll
            for (int p = 0; p < 4; p++)
#pragma unroll
                for (int mt = 0; mt < 2; mt++) {
                    MMA16816(acc[mt][2 * p],     ah[mt], bh[p][0], bh[p][1]);
                    MMA16816(acc[mt][2 * p + 1], ah[mt], bh[p][2], bh[p][3]);
                }
#pragma unroll
            for (int p = 0; p < 4; p++)
#pragma unroll
                for (int mt = 0; mt < 2; mt++) {
                    MMA16816(acc[mt][2 * p],     ah[mt], bl[p][0], bl[p][1]);
                    MMA16816(acc[mt][2 * p + 1], ah[mt], bl[p][2], bl[p][3]);
                }
#pragma unroll
            for (int p = 0; p < 4; p++)
#pragma unroll
                for (int mt = 0; mt < 2; mt++) {
                    MMA16816(acc[mt][2 * p],     al[mt], bh[p][0], bh[p][1]);
                    MMA16816(acc[mt][2 * p + 1], al[mt], bh[p][2], bh[p][3]);
                }
        }

        if (hasNext) store_chunk((c + 1) & 1);  // other stage: no race with compute(c)
        __syncthreads();                        // single barrier per chunk
    }

    // ---- epilogue
    const int fr = lane >> 2, fc = (lane & 3) * 2;
#pragma unroll
    for (int mt = 0; mt < 2; mt++) {
        int r0 = m0 + wm + mt * 16 + fr;
#pragma unroll
        for (int nt = 0; nt < 8; nt++) {
            int cbase = wn + nt * 8 + fc;
            if (r0 < M)
                *(float2*)(C + (size_t)r0 * 128 + cbase) =
                    make_float2(acc[mt][nt][0], acc[mt][nt][1]);
            if (r0 + 8 < M)
                *(float2*)(C + (size_t)(r0 + 8) * 128 + cbase) =
                    make_float2(acc[mt][nt][2], acc[mt][nt][3]);
        }
    }
}

// ---------------- CSR SpMM + bias (+relu) ----------------
__global__ __launch_bounds__(256) void k_spmm(const float* __restrict__ S,
                                              float* __restrict__ H,
                                              const float* __restrict__ bias,
                                              int F, int FsQ, int do_relu) {
    int wid  = (blockIdx.x * 256 + threadIdx.x) >> 5;
    if (wid >= NN) return;
    int lane = threadIdx.x & 31;
    int f    = lane * 4;
    if (f >= F) return;
    int fq = f >> 2, Fq = F >> 2;

    int beg = g_rp[wid], end = g_rp[wid + 1];
    const float4* Sv = (const float4*)S;
    float4 acc = make_float4(0.f, 0.f, 0.f, 0.f);
#pragma unroll 4
    for (int e = beg; e < end; e++) {
        int   c = g_cs[e];
        float w = g_ws[e];
        float4 v = Sv[(size_t)c * FsQ + fq];
        acc.x += w * v.x; acc.y += w * v.y; acc.z += w * v.z; acc.w += w * v.w;
    }
    float4 b = ((const float4*)bias)[fq];
    acc.x += b.x; acc.y += b.y; acc.z += b.z; acc.w += b.w;
    if (do_relu) {
        acc.x = fmaxf(acc.x, 0.f); acc.y = fmaxf(acc.y, 0.f);
        acc.z = fmaxf(acc.z, 0.f); acc.w = fmaxf(acc.w, 0.f);
    }
    ((float4*)H)[(size_t)wid * Fq + fq] = acc;
}

// ---------------- log_softmax over 40 classes ----------------
__global__ __launch_bounds__(256) void k_lsm(float* __restrict__ out) {
    int wid = (blockIdx.x * 256 + threadIdx.x) >> 5;
    if (wid >= NN) return;
    int lane = threadIdx.x & 31;
    const float* a = g_A4 + (size_t)wid * NC;
    float v0 = a[lane];
    float v1 = (lane + 32 < NC) ? a[lane + 32] : -1e30f;
    float m = fmaxf(v0, v1);
#pragma unroll
    for (int o = 16; o; o >>= 1) m = fmaxf(m, __shfl_xor_sync(0xffffffffu, m, o));
    float s = expf(v0 - m) + ((lane + 32 < NC) ? expf(v1 - m) : 0.f);
#pragma unroll
    for (int o = 16; o; o >>= 1) s += __shfl_xor_sync(0xffffffffu, s, o);
    float l = m + logf(s);
    out[(size_t)wid * NC + lane] = v0 - l;
    if (lane + 32 < NC) out[(size_t)wid * NC + lane + 32] = v1 - l;
}

// ---------------- launch ----------------
extern "C" void kernel_launch(void* const* d_in, const int* in_sizes, int n_in,
                              void* d_out, int out_size) {
    const float* x  = (const float*)d_in[0];
    const int*   row = (const int*)d_in[1];
    const int*   col = (const int*)d_in[2];
    const float* ew  = (const float*)d_in[3];
    const float* W1 = (const float*)d_in[4];  const float* b1 = (const float*)d_in[5];
    const float* W2 = (const float*)d_in[6];  const float* b2 = (const float*)d_in[7];
    const float* W3 = (const float*)d_in[8];  const float* b3 = (const float*)d_in[9];
    const float* W4 = (const float*)d_in[10]; const float* b4 = (const float*)d_in[11];
    float* out = (float*)d_out;

    void *pS, *pH, *pH2, *pA4, *pW4p;
    cudaGetSymbolAddress(&pS,   g_S);
    cudaGetSymbolAddress(&pH,   g_H);
    cudaGetSymbolAddress(&pH2,  g_H2);
    cudaGetSymbolAddress(&pA4,  g_A4);
    cudaGetSymbolAddress(&pW4p, g_W4p);
    float* S   = (float*)pS;
    float* H   = (float*)pH;
    float* H2  = (float*)pH2;
    float* A4  = (float*)pA4;
    float* W4p = (float*)pW4p;

    cudaFuncSetAttribute(k_gemm_mma, cudaFuncAttributeMaxDynamicSharedMemorySize, GEMM_SMEM);

    const int EB = (NE + 255) / 256;
    const int GM = (NN + 127) / 128;     // 782 row tiles
    const int SB = (NN + 7) / 8;         // warp-per-row

    // CSR build interleaved with layer-1 GEMM (same launch order as R8 so the
    // ncu window lands on gemm1 again)
    k_zero<<<(NN + 255) / 256, 256>>>();
    k_count<<<EB, 256>>>(row);
    k_scan1<<<NBLK, SCAN_B>>>();
    k_gemm_mma<<<GM, 256, GEMM_SMEM>>>(x, W1, S, NN, NF);      // layer-1 support
    k_scan2<<<1, 256>>>();
    k_scan3<<<NBLK, SCAN_B>>>();
    k_scatter<<<EB, 256>>>(row, col, ew);
    k_padw4<<<64, 256>>>(W4);

    // layer 1 aggregate
    k_spmm<<<SB, 256>>>(S, H, b1, NH, NH / 4, 1);
    // layer 2
    k_gemm_mma<<<GM, 256, GEMM_SMEM>>>(H, W2, S, NN, NH);
    k_spmm<<<SB, 256>>>(S, H2, b2, NH, NH / 4, 1);
    // layer 3
    k_gemm_mma<<<GM, 256, GEMM_SMEM>>>(H2, W3, S, NN, NH);
    k_spmm<<<SB, 256>>>(S, H, b3, NH, NH / 4, 1);
    // layer 4 (padded to 128-wide tensor GEMM) + log_softmax
    k_gemm_mma<<<GM, 256, GEMM_SMEM>>>(H, W4p, S, NN, NH);
    k_spmm<<<SB, 256>>>(S, A4, b4, NC, 128 / 4, 0);
    k_lsm<<<SB, 256>>>(out);
}